// round 10
// baseline (speedup 1.0000x reference)
#include <cuda_runtime.h>
#include <math.h>
#include <stdint.h>

#define B_      8
#define NSEQ    4096
#define DIM     512
#define DH      64
#define HEADS   8
#define TRIPLE  1536
#define MROWS   (B_ * NSEQ)          // 32768
#define NSPLIT  8

// ---------------- scratch (device globals: allocation-free) ----------------
static __device__ float g_rowscale[MROWS];                        // sqrt(512)/||x_row||
static __device__ float g_qkv[(size_t)MROWS * TRIPLE];            // 192 MB
static __device__ float g_rnorm[B_ * 1024];                       // 1/||q_f||, 1/||k_f|| over n
static __device__ float g_part[(size_t)NSPLIT * 64 * DH * DH];    // partial Gram sums, 8 MB
static __device__ float g_attn[(size_t)64 * DH * DH];             // softmaxed attn, 1 MB
static __device__ float g_y[(size_t)MROWS * DIM];                 // attn output, [b,n,h*d], 64 MB

// ---------------- K0: per-row RMSNorm scale ----------------
__global__ void rownorm_kernel(const float* __restrict__ x) {
    int row = blockIdx.x;
    int t = threadIdx.x;  // 128 threads, 4 floats each
    float4 v = reinterpret_cast<const float4*>(x)[(size_t)row * (DIM / 4) + t];
    float ss = v.x * v.x + v.y * v.y + v.z * v.z + v.w * v.w;
#pragma unroll
    for (int o = 16; o > 0; o >>= 1) ss += __shfl_down_sync(0xffffffffu, ss, o);
    __shared__ float ws[4];
    if ((t & 31) == 0) ws[t >> 5] = ss;
    __syncthreads();
    if (t == 0) {
        float tot = ws[0] + ws[1] + ws[2] + ws[3];
        g_rowscale[row] = 22.62741699796952f / fmaxf(sqrtf(tot), 1e-12f); // sqrt(512)/||x||
    }
}

// ------- generic 128x128x16 fp32 GEMM, double-buffered smem, FFMA2 inner loop -------
// A row-major [M,K], B row-major [K,N]. Optionally fuses RMSNorm scaling on A.
template <bool FUSE>
__global__ __launch_bounds__(256, 2) void sgemm128(
    const float* __restrict__ A, const float* __restrict__ Bm,
    float* __restrict__ C, int M, int Nn, int K, const float* __restrict__ gamma)
{
    __shared__ float As[2][16][132];   // [buf][k][m], padded
    __shared__ float Bs[2][16][128];   // [buf][k][n]
    int tid = threadIdx.x;
    int m0 = blockIdx.y * 128;
    int n0 = blockIdx.x * 128;
    int aRow = tid >> 1;
    int aCol = (tid & 1) << 3;            // 0 or 8
    int bRow = tid >> 4;                  // 0..15
    int bCol = (tid & 15) << 3;           // 0..120
    const float* Ap = A + (size_t)(m0 + aRow) * K + aCol;
    const float* Bp = Bm + (size_t)bRow * Nn + n0 + bCol;
    float rs = FUSE ? g_rowscale[m0 + aRow] : 0.0f;
    int tx = tid & 15, ty = tid >> 4;

    // packed fp32 accumulators: acc2[i][j] = (acc[i][2j], acc[i][2j+1])
    unsigned long long acc2[8][4];
#pragma unroll
    for (int i = 0; i < 8; i++)
#pragma unroll
        for (int j = 0; j < 4; j++) acc2[i][j] = 0ull;

    float4 a0, a1, b0, b1;
    // prologue: fetch tile 0 into registers, commit to buffer 0
    a0 = *reinterpret_cast<const float4*>(Ap);
    a1 = *reinterpret_cast<const float4*>(Ap + 4);
    b0 = *reinterpret_cast<const float4*>(Bp);
    b1 = *reinterpret_cast<const float4*>(Bp + 4);
    if (FUSE) {
        float4 g0 = *reinterpret_cast<const float4*>(gamma + aCol);
        float4 g1 = *reinterpret_cast<const float4*>(gamma + aCol + 4);
        a0.x *= rs * g0.x; a0.y *= rs * g0.y; a0.z *= rs * g0.z; a0.w *= rs * g0.w;
        a1.x *= rs * g1.x; a1.y *= rs * g1.y; a1.z *= rs * g1.z; a1.w *= rs * g1.w;
    }
    As[0][aCol + 0][aRow] = a0.x; As[0][aCol + 1][aRow] = a0.y;
    As[0][aCol + 2][aRow] = a0.z; As[0][aCol + 3][aRow] = a0.w;
    As[0][aCol + 4][aRow] = a1.x; As[0][aCol + 5][aRow] = a1.y;
    As[0][aCol + 6][aRow] = a1.z; As[0][aCol + 7][aRow] = a1.w;
    *reinterpret_cast<float4*>(&Bs[0][bRow][bCol])     = b0;
    *reinterpret_cast<float4*>(&Bs[0][bRow][bCol + 4]) = b1;
    __syncthreads();

    int buf = 0;
    for (int k0 = 0; k0 < K; k0 += 16) {
        int k1 = k0 + 16;
        bool more = (k1 < K);
        // prefetch next tile into registers (overlaps with compute below)
        if (more) {
            a0 = *reinterpret_cast<const float4*>(Ap + k1);
            a1 = *reinterpret_cast<const float4*>(Ap + k1 + 4);
            b0 = *reinterpret_cast<const float4*>(Bp + (size_t)k1 * Nn);
            b1 = *reinterpret_cast<const float4*>(Bp + (size_t)k1 * Nn + 4);
            if (FUSE) {
                float4 g0 = *reinterpret_cast<const float4*>(gamma + k1 + aCol);
                float4 g1 = *reinterpret_cast<const float4*>(gamma + k1 + aCol + 4);
                a0.x *= rs * g0.x; a0.y *= rs * g0.y; a0.z *= rs * g0.z; a0.w *= rs * g0.w;
                a1.x *= rs * g1.x; a1.y *= rs * g1.y; a1.z *= rs * g1.z; a1.w *= rs * g1.w;
            }
        }

#pragma unroll
        for (int kk = 0; kk < 16; kk++) {
            uint32_t ar[8];                 // A fragment as raw bits
            unsigned long long bb[4];       // B fragment as 4 packed f32x2 pairs
            *reinterpret_cast<float4*>(&ar[0]) =
                *reinterpret_cast<const float4*>(&As[buf][kk][ty * 8]);
            *reinterpret_cast<float4*>(&ar[4]) =
                *reinterpret_cast<const float4*>(&As[buf][kk][ty * 8 + 4]);
            const unsigned long long* bp =
                reinterpret_cast<const unsigned long long*>(&Bs[buf][kk][tx * 8]);
            bb[0] = bp[0]; bb[1] = bp[1]; bb[2] = bp[2]; bb[3] = bp[3];
#pragma unroll
            for (int i = 0; i < 8; i++) {
                unsigned long long a2;
                asm("mov.b64 %0, {%1, %1};" : "=l"(a2) : "r"(ar[i]));
#pragma unroll
                for (int j = 0; j < 4; j++)
                    asm("fma.rn.f32x2 %0, %1, %2, %0;"
                        : "+l"(acc2[i][j]) : "l"(a2), "l"(bb[j]));
            }
        }

        if (more) {
            int nb = buf ^ 1;   // write other buffer: safe while peers compute from buf
            As[nb][aCol + 0][aRow] = a0.x; As[nb][aCol + 1][aRow] = a0.y;
            As[nb][aCol + 2][aRow] = a0.z; As[nb][aCol + 3][aRow] = a0.w;
            As[nb][aCol + 4][aRow] = a1.x; As[nb][aCol + 5][aRow] = a1.y;
            As[nb][aCol + 6][aRow] = a1.z; As[nb][aCol + 7][aRow] = a1.w;
            *reinterpret_cast<float4*>(&Bs[nb][bRow][bCol])     = b0;
            *reinterpret_cast<float4*>(&Bs[nb][bRow][bCol + 4]) = b1;
            __syncthreads();
            buf = nb;
        }
    }
#pragma unroll
    for (int i = 0; i < 8; i++) {
        float2 p0 = *reinterpret_cast<float2*>(&acc2[i][0]);
        float2 p1 = *reinterpret_cast<float2*>(&acc2[i][1]);
        float2 p2 = *reinterpret_cast<float2*>(&acc2[i][2]);
        float2 p3 = *reinterpret_cast<float2*>(&acc2[i][3]);
        float* cp = C + (size_t)(m0 + ty * 8 + i) * Nn + n0 + tx * 8;
        *reinterpret_cast<float4*>(cp)     = make_float4(p0.x, p0.y, p1.x, p1.y);
        *reinterpret_cast<float4*>(cp + 4) = make_float4(p2.x, p2.y, p3.x, p3.y);
    }
}

// ---------------- K2: column L2 norms of q,k features (over n) ----------------
__global__ void colnorm_kernel() {
    int b = blockIdx.y;
    int f = blockIdx.x * 32 + (threadIdx.x & 31);   // feature in [0,1024)
    int ty = threadIdx.x >> 5;                       // 0..7
    const float* base = g_qkv + (size_t)b * NSEQ * TRIPLE + f;
    float ss = 0.0f;
    for (int n = ty; n < NSEQ; n += 8) {
        float v = base[(size_t)n * TRIPLE];
        ss += v * v;
    }
    __shared__ float red[8][33];
    red[ty][threadIdx.x & 31] = ss;
    __syncthreads();
    if (ty == 0) {
        float s = 0.0f;
#pragma unroll
        for (int i = 0; i < 8; i++) s += red[i][threadIdx.x & 31];
        g_rnorm[b * 1024 + f] = 1.0f / fmaxf(sqrtf(s), 1e-12f);
    }
}

// ---------------- K3a: partial Gram matrices sim[d][e] = sum_n q[d,n]k[e,n] ----------------
__global__ __launch_bounds__(256, 4) void sim_partial_kernel() {
    int bh = blockIdx.x;
    int b = bh >> 3, h = bh & 7;
    int split = blockIdx.y;
    __shared__ float qs[32][68];   // [n_local][d]
    __shared__ float ks[32][68];   // [n_local][e]
    int tid = threadIdx.x;
    int tx = tid & 15, ty = tid >> 4;
    int e0 = tx * 4, d0 = ty * 4;
    int ld4 = tid & 15;   // d4 group
    int lnl = tid >> 4;   // n_local base
    int qoff = h * 64;
    int koff = 512 + h * 64;
    const float* base = g_qkv + (size_t)b * NSEQ * TRIPLE;

    float c[4][4];
#pragma unroll
    for (int i = 0; i < 4; i++)
#pragma unroll
        for (int j = 0; j < 4; j++) c[i][j] = 0.0f;

    int nbeg = split * (NSEQ / NSPLIT);
    int nend = nbeg + (NSEQ / NSPLIT);
    for (int n0 = nbeg; n0 < nend; n0 += 32) {
#pragma unroll
        for (int p = 0; p < 2; p++) {
            int nl = lnl + p * 16;
            const float* rowp = base + (size_t)(n0 + nl) * TRIPLE;
            float4 q4 = *reinterpret_cast<const float4*>(rowp + qoff + ld4 * 4);
            float4 k4 = *reinterpret_cast<const float4*>(rowp + koff + ld4 * 4);
            *reinterpret_cast<float4*>(&qs[nl][ld4 * 4]) = q4;
            *reinterpret_cast<float4*>(&ks[nl][ld4 * 4]) = k4;
        }
        __syncthreads();
#pragma unroll
        for (int nl = 0; nl < 32; nl++) {
            float4 a  = *reinterpret_cast<const float4*>(&qs[nl][d0]);
            float4 bb = *reinterpret_cast<const float4*>(&ks[nl][e0]);
            c[0][0] += a.x * bb.x; c[0][1] += a.x * bb.y; c[0][2] += a.x * bb.z; c[0][3] += a.x * bb.w;
            c[1][0] += a.y * bb.x; c[1][1] += a.y * bb.y; c[1][2] += a.y * bb.z; c[1][3] += a.y * bb.w;
            c[2][0] += a.z * bb.x; c[2][1] += a.z * bb.y; c[2][2] += a.z * bb.z; c[2][3] += a.z * bb.w;
            c[3][0] += a.w * bb.x; c[3][1] += a.w * bb.y; c[3][2] += a.w * bb.z; c[3][3] += a.w * bb.w;
        }
        __syncthreads();
    }
    float* outp = g_part + (((size_t)split * 64 + bh) * 64) * 64;
#pragma unroll
    for (int i = 0; i < 4; i++)
        *reinterpret_cast<float4*>(outp + (size_t)(d0 + i) * 64 + e0) =
            make_float4(c[i][0], c[i][1], c[i][2], c[i][3]);
}

// ---------------- K3b: reduce partials + scale + softmax over e ----------------
__global__ void softmax_kernel(const float* __restrict__ temperature) {
    int bh = blockIdx.x, b = bh >> 3, h = bh & 7;
    int d = threadIdx.x;   // 64 threads
    __shared__ float rk_s[64];
    rk_s[d] = g_rnorm[b * 1024 + 512 + h * 64 + d];
    __syncthreads();
    float rq = g_rnorm[b * 1024 + h * 64 + d];
    float pref = 8.0f * expf(temperature[h]) * rq;   // SCALE * exp(tau_h) / ||q_d||
    float row[64];
    float mx = -1e30f;
#pragma unroll
    for (int e = 0; e < 64; e++) {
        float s = 0.0f;
#pragma unroll
        for (int sp = 0; sp < NSPLIT; sp++)
            s += g_part[(((size_t)sp * 64 + bh) * 64 + d) * 64 + e];
        s *= pref * rk_s[e];
        row[e] = s;
        mx = fmaxf(mx, s);
    }
    float sum = 0.0f;
#pragma unroll
    for (int e = 0; e < 64; e++) {
        float v = expf(row[e] - mx);
        row[e] = v;
        sum += v;
    }
    float inv = 1.0f / sum;
#pragma unroll
    for (int e = 0; e < 64; e++)
        g_attn[((size_t)bh * 64 + d) * 64 + e] = row[e] * inv;
}

// ---------------- K3c: out[d,n] = sum_e attn[d,e] v[e,n], stored as y[b,n,h*64+d] ----------------
__global__ __launch_bounds__(256) void av_kernel() {
    int bh = blockIdx.y, b = bh >> 3, h = bh & 7;
    int n0 = blockIdx.x * 64;
    __shared__ float attn_s[64][68];  // [e][d]
    __shared__ float vs[64][68];      // [e][n_local]
    int tid = threadIdx.x;
    {
        int d = tid >> 2, e0 = (tid & 3) * 16;
        const float* ap = g_attn + ((size_t)bh * 64 + d) * 64 + e0;
#pragma unroll
        for (int i = 0; i < 16; i++) attn_s[e0 + i][d] = ap[i];
    }
    {
        int e4 = tid & 15, lnl = tid >> 4;
        const float* vbase = g_qkv + (size_t)b * NSEQ * TRIPLE + 1024 + h * 64 + e4 * 4;
#pragma unroll
        for (int p = 0; p < 4; p++) {
            int nl = lnl + p * 16;
            float4 v4 = *reinterpret_cast<const float4*>(vbase + (size_t)(n0 + nl) * TRIPLE);
            vs[e4 * 4 + 0][nl] = v4.x;
            vs[e4 * 4 + 1][nl] = v4.y;
            vs[e4 * 4 + 2][nl] = v4.z;
            vs[e4 * 4 + 3][nl] = v4.w;
        }
    }
    __syncthreads();
    int tx = tid & 15, ty = tid >> 4;
    int d0 = tx * 4, nl0 = ty * 4;
    float c[4][4];
#pragma unroll
    for (int i = 0; i < 4; i++)
#pragma unroll
        for (int j = 0; j < 4; j++) c[i][j] = 0.0f;
#pragma unroll
    for (int e = 0; e < 64; e++) {
        float4 a  = *reinterpret_cast<const float4*>(&attn_s[e][d0]);
        float4 v4 = *reinterpret_cast<const float4*>(&vs[e][nl0]);
        c[0][0] += a.x * v4.x; c[0][1] += a.x * v4.y; c[0][2] += a.x * v4.z; c[0][3] += a.x * v4.w;
        c[1][0] += a.y * v4.x; c[1][1] += a.y * v4.y; c[1][2] += a.y * v4.z; c[1][3] += a.y * v4.w;
        c[2][0] += a.z * v4.x; c[2][1] += a.z * v4.y; c[2][2] += a.z * v4.z; c[2][3] += a.z * v4.w;
        c[3][0] += a.w * v4.x; c[3][1] += a.w * v4.y; c[3][2] += a.w * v4.z; c[3][3] += a.w * v4.w;
    }
#pragma unroll
    for (int j = 0; j < 4; j++) {
        float4 o = make_float4(c[0][j], c[1][j], c[2][j], c[3][j]);
        *reinterpret_cast<float4*>(g_y + (size_t)(b * NSEQ + n0 + nl0 + j) * DIM + h * 64 + d0) = o;
    }
}

// ---------------- launch ----------------
extern "C" void kernel_launch(void* const* d_in, const int* in_sizes, int n_in,
                              void* d_out, int out_size) {
    const float* x           = (const float*)d_in[0];
    const float* gamma       = (const float*)d_in[1];
    const float* w_qkv       = (const float*)d_in[2];
    const float* temperature = (const float*)d_in[3];
    const float* w_out       = (const float*)d_in[4];
    float* out = (float*)d_out;

    float *p_qkv = nullptr, *p_y = nullptr;
    cudaGetSymbolAddress((void**)&p_qkv, g_qkv);
    cudaGetSymbolAddress((void**)&p_y, g_y);

    // 1) row norms of x
    rownorm_kernel<<<MROWS, 128>>>(x);
    // 2) qkv = RMSNorm(x) @ w_qkv   (norm fused into A-loads)
    sgemm128<true><<<dim3(TRIPLE / 128, MROWS / 128), 256>>>(
        x, w_qkv, p_qkv, MROWS, TRIPLE, DIM, gamma);
    // 3) per-(b,feature) L2 norms of q,k over n
    colnorm_kernel<<<dim3(32, B_), 256>>>();
    // 4) partial Gram matrices
    sim_partial_kernel<<<dim3(64, NSPLIT), 256>>>();
    // 5) reduce + scale + softmax
    softmax_kernel<<<64, 64>>>(temperature);
    // 6) attn @ v -> y in [b,n,h*d] layout
    av_kernel<<<dim3(NSEQ / 64, 64), 256>>>();
    // 7) out = y @ w_out
    sgemm128<false><<<dim3(DIM / 128, MROWS / 128), 256>>>(
        p_y, w_out, out, MROWS, DIM, DIM, nullptr);
}

// round 11
// speedup vs baseline: 1.4397x; 1.4397x over previous
#include <cuda_runtime.h>
#include <cuda_bf16.h>
#include <mma.h>
#include <math.h>
#include <stdint.h>

#define B_      8
#define NSEQ    4096
#define DIM     512
#define DH      64
#define HEADS   8
#define TRIPLE  1536
#define MROWS   (B_ * NSEQ)          // 32768
#define NSPLIT  8

// ---------------- scratch (device globals: allocation-free) ----------------
static __device__ float g_rowscale[MROWS];
static __device__ float g_qkv[(size_t)MROWS * TRIPLE];            // 192 MB
static __device__ float g_rnorm[B_ * 1024];
static __device__ float g_part[(size_t)NSPLIT * 64 * DH * DH];
static __device__ float g_attn[(size_t)64 * DH * DH];
static __device__ float g_y[(size_t)MROWS * DIM];                 // 64 MB
// bf16 hi/lo operand splits for tensor-core GEMMs
static __device__ __nv_bfloat16 g_ahi[(size_t)MROWS * DIM];       // 32 MB
static __device__ __nv_bfloat16 g_alo[(size_t)MROWS * DIM];       // 32 MB
static __device__ __nv_bfloat16 g_yhi[(size_t)MROWS * DIM];       // 32 MB
static __device__ __nv_bfloat16 g_ylo[(size_t)MROWS * DIM];       // 32 MB
static __device__ __nv_bfloat16 g_w1hi[(size_t)DIM * TRIPLE];     // w_qkv [k][n]
static __device__ __nv_bfloat16 g_w1lo[(size_t)DIM * TRIPLE];
static __device__ __nv_bfloat16 g_w2hi[(size_t)DIM * DIM];        // w_out [k][n]
static __device__ __nv_bfloat16 g_w2lo[(size_t)DIM * DIM];

// ---------------- K0: per-row RMSNorm scale ----------------
__global__ void rownorm_kernel(const float* __restrict__ x) {
    int row = blockIdx.x;
    int t = threadIdx.x;
    float4 v = reinterpret_cast<const float4*>(x)[(size_t)row * (DIM / 4) + t];
    float ss = v.x * v.x + v.y * v.y + v.z * v.z + v.w * v.w;
#pragma unroll
    for (int o = 16; o > 0; o >>= 1) ss += __shfl_down_sync(0xffffffffu, ss, o);
    __shared__ float ws[4];
    if ((t & 31) == 0) ws[t >> 5] = ss;
    __syncthreads();
    if (t == 0) {
        float tot = ws[0] + ws[1] + ws[2] + ws[3];
        g_rowscale[row] = 22.62741699796952f / fmaxf(sqrtf(tot), 1e-12f);
    }
}

// ---------------- K1a: A = RMSNorm(x) -> hi/lo bf16 split ----------------
__global__ void convert_a_kernel(const float* __restrict__ x, const float* __restrict__ gamma) {
    size_t i = (size_t)blockIdx.x * blockDim.x + threadIdx.x;   // float4 index
    float4 v = reinterpret_cast<const float4*>(x)[i];
    float rs = g_rowscale[i >> 7];                               // DIM/4 = 128 float4/row
    float4 g = reinterpret_cast<const float4*>(gamma)[i & 127];
    float f[4] = {v.x * rs * g.x, v.y * rs * g.y, v.z * rs * g.z, v.w * rs * g.w};
    __nv_bfloat16 h[4], l[4];
#pragma unroll
    for (int j = 0; j < 4; j++) {
        h[j] = __float2bfloat16(f[j]);
        l[j] = __float2bfloat16(f[j] - __bfloat162float(h[j]));
    }
    reinterpret_cast<uint2*>(g_ahi)[i] = *reinterpret_cast<uint2*>(h);
    reinterpret_cast<uint2*>(g_alo)[i] = *reinterpret_cast<uint2*>(l);
}

// ---------------- generic elementwise fp32 -> bf16 hi/lo split ----------------
__global__ void split_kernel(const float* __restrict__ src,
                             __nv_bfloat16* __restrict__ hi,
                             __nv_bfloat16* __restrict__ lo) {
    size_t i = (size_t)blockIdx.x * blockDim.x + threadIdx.x;   // float4 index
    float4 v = reinterpret_cast<const float4*>(src)[i];
    float f[4] = {v.x, v.y, v.z, v.w};
    __nv_bfloat16 h[4], l[4];
#pragma unroll
    for (int j = 0; j < 4; j++) {
        h[j] = __float2bfloat16(f[j]);
        l[j] = __float2bfloat16(f[j] - __bfloat162float(h[j]));
    }
    reinterpret_cast<uint2*>(hi)[i] = *reinterpret_cast<uint2*>(h);
    reinterpret_cast<uint2*>(lo)[i] = *reinterpret_cast<uint2*>(l);
}

// ---------------- WMMA bf16x3 GEMM: C[m][n] = sum_k A[m,k]*B[k,n] ----------------
// A row-major [M,K] as hi/lo bf16; B row-major [K,N] as hi/lo bf16; C fp32.
// CTA tile 128x64, BK=32, 8 warps (4x2), each warp 32x32 (2x2 wmma frags).
__global__ __launch_bounds__(256) void wmma_gemm(
    const __nv_bfloat16* __restrict__ Ahi, const __nv_bfloat16* __restrict__ Alo,
    const __nv_bfloat16* __restrict__ Bhi, const __nv_bfloat16* __restrict__ Blo,
    float* __restrict__ C, int Nn, int K)
{
    using namespace nvcuda;
    __shared__ __nv_bfloat16 sAh[128][40];   // [m][k], pad 8
    __shared__ __nv_bfloat16 sAl[128][40];
    __shared__ __nv_bfloat16 sBh[32][72];    // [k][n], pad 8
    __shared__ __nv_bfloat16 sBl[32][72];
    int tid = threadIdx.x, wid = tid >> 5;
    int m0 = blockIdx.y * 128, n0 = blockIdx.x * 64;
    int wm = wid & 3, wn = wid >> 2;         // warp -> (m-quad, n-half)

    wmma::fragment<wmma::accumulator, 16, 16, 16, float> acc[2][2];
#pragma unroll
    for (int i = 0; i < 2; i++)
#pragma unroll
        for (int j = 0; j < 2; j++) wmma::fill_fragment(acc[i][j], 0.0f);

    // A tile loader: thread -> row tid/2, 16 bf16 at col (tid&1)*16
    int arow = tid >> 1, acol = (tid & 1) << 4;
    // B tile loader: thread -> row tid/8, 8 bf16 at col (tid&7)*8
    int brow = tid >> 3, bcol = (tid & 7) << 3;

    for (int k0 = 0; k0 < K; k0 += 32) {
        const uint4* pAh = reinterpret_cast<const uint4*>(Ahi + (size_t)(m0 + arow) * K + k0 + acol);
        const uint4* pAl = reinterpret_cast<const uint4*>(Alo + (size_t)(m0 + arow) * K + k0 + acol);
        uint4 vh0 = pAh[0], vh1 = pAh[1], vl0 = pAl[0], vl1 = pAl[1];
        *reinterpret_cast<uint4*>(&sAh[arow][acol])     = vh0;
        *reinterpret_cast<uint4*>(&sAh[arow][acol + 8]) = vh1;
        *reinterpret_cast<uint4*>(&sAl[arow][acol])     = vl0;
        *reinterpret_cast<uint4*>(&sAl[arow][acol + 8]) = vl1;
        const uint4* pBh = reinterpret_cast<const uint4*>(Bhi + (size_t)(k0 + brow) * Nn + n0 + bcol);
        const uint4* pBl = reinterpret_cast<const uint4*>(Blo + (size_t)(k0 + brow) * Nn + n0 + bcol);
        *reinterpret_cast<uint4*>(&sBh[brow][bcol]) = pBh[0];
        *reinterpret_cast<uint4*>(&sBl[brow][bcol]) = pBl[0];
        __syncthreads();

#pragma unroll
        for (int ks = 0; ks < 32; ks += 16) {
            wmma::fragment<wmma::matrix_a, 16, 16, 16, __nv_bfloat16, wmma::row_major> ah[2], al[2];
            wmma::fragment<wmma::matrix_b, 16, 16, 16, __nv_bfloat16, wmma::row_major> bh[2], bl[2];
#pragma unroll
            for (int i = 0; i < 2; i++) {
                wmma::load_matrix_sync(ah[i], &sAh[wm * 32 + i * 16][ks], 40);
                wmma::load_matrix_sync(al[i], &sAl[wm * 32 + i * 16][ks], 40);
            }
#pragma unroll
            for (int j = 0; j < 2; j++) {
                wmma::load_matrix_sync(bh[j], &sBh[ks][wn * 32 + j * 16], 72);
                wmma::load_matrix_sync(bl[j], &sBl[ks][wn * 32 + j * 16], 72);
            }
#pragma unroll
            for (int i = 0; i < 2; i++)
#pragma unroll
                for (int j = 0; j < 2; j++) {
                    wmma::mma_sync(acc[i][j], ah[i], bh[j], acc[i][j]);
                    wmma::mma_sync(acc[i][j], ah[i], bl[j], acc[i][j]);
                    wmma::mma_sync(acc[i][j], al[i], bh[j], acc[i][j]);
                }
        }
        __syncthreads();
    }
#pragma unroll
    for (int i = 0; i < 2; i++)
#pragma unroll
        for (int j = 0; j < 2; j++)
            wmma::store_matrix_sync(
                C + (size_t)(m0 + wm * 32 + i * 16) * Nn + n0 + wn * 32 + j * 16,
                acc[i][j], Nn, wmma::mem_row_major);
}

// ---------------- K2: column L2 norms of q,k features (over n) ----------------
__global__ void colnorm_kernel() {
    int b = blockIdx.y;
    int f = blockIdx.x * 32 + (threadIdx.x & 31);
    int ty = threadIdx.x >> 5;
    const float* base = g_qkv + (size_t)b * NSEQ * TRIPLE + f;
    float ss = 0.0f;
    for (int n = ty; n < NSEQ; n += 8) {
        float v = base[(size_t)n * TRIPLE];
        ss += v * v;
    }
    __shared__ float red[8][33];
    red[ty][threadIdx.x & 31] = ss;
    __syncthreads();
    if (ty == 0) {
        float s = 0.0f;
#pragma unroll
        for (int i = 0; i < 8; i++) s += red[i][threadIdx.x & 31];
        g_rnorm[b * 1024 + f] = 1.0f / fmaxf(sqrtf(s), 1e-12f);
    }
}

// ---------------- K3a: partial Gram matrices sim[d][e] = sum_n q[d,n]k[e,n] ----------------
__global__ __launch_bounds__(256, 4) void sim_partial_kernel() {
    int bh = blockIdx.x;
    int b = bh >> 3, h = bh & 7;
    int split = blockIdx.y;
    __shared__ float qs[32][68];
    __shared__ float ks[32][68];
    int tid = threadIdx.x;
    int tx = tid & 15, ty = tid >> 4;
    int e0 = tx * 4, d0 = ty * 4;
    int ld4 = tid & 15;
    int lnl = tid >> 4;
    int qoff = h * 64;
    int koff = 512 + h * 64;
    const float* base = g_qkv + (size_t)b * NSEQ * TRIPLE;

    float c[4][4];
#pragma unroll
    for (int i = 0; i < 4; i++)
#pragma unroll
        for (int j = 0; j < 4; j++) c[i][j] = 0.0f;

    int nbeg = split * (NSEQ / NSPLIT);
    int nend = nbeg + (NSEQ / NSPLIT);
    for (int n0 = nbeg; n0 < nend; n0 += 32) {
#pragma unroll
        for (int p = 0; p < 2; p++) {
            int nl = lnl + p * 16;
            const float* rowp = base + (size_t)(n0 + nl) * TRIPLE;
            float4 q4 = *reinterpret_cast<const float4*>(rowp + qoff + ld4 * 4);
            float4 k4 = *reinterpret_cast<const float4*>(rowp + koff + ld4 * 4);
            *reinterpret_cast<float4*>(&qs[nl][ld4 * 4]) = q4;
            *reinterpret_cast<float4*>(&ks[nl][ld4 * 4]) = k4;
        }
        __syncthreads();
#pragma unroll
        for (int nl = 0; nl < 32; nl++) {
            float4 a  = *reinterpret_cast<const float4*>(&qs[nl][d0]);
            float4 bb = *reinterpret_cast<const float4*>(&ks[nl][e0]);
            c[0][0] += a.x * bb.x; c[0][1] += a.x * bb.y; c[0][2] += a.x * bb.z; c[0][3] += a.x * bb.w;
            c[1][0] += a.y * bb.x; c[1][1] += a.y * bb.y; c[1][2] += a.y * bb.z; c[1][3] += a.y * bb.w;
            c[2][0] += a.z * bb.x; c[2][1] += a.z * bb.y; c[2][2] += a.z * bb.z; c[2][3] += a.z * bb.w;
            c[3][0] += a.w * bb.x; c[3][1] += a.w * bb.y; c[3][2] += a.w * bb.z; c[3][3] += a.w * bb.w;
        }
        __syncthreads();
    }
    float* outp = g_part + (((size_t)split * 64 + bh) * 64) * 64;
#pragma unroll
    for (int i = 0; i < 4; i++)
        *reinterpret_cast<float4*>(outp + (size_t)(d0 + i) * 64 + e0) =
            make_float4(c[i][0], c[i][1], c[i][2], c[i][3]);
}

// ---------------- K3b: reduce partials + scale + softmax over e ----------------
__global__ void softmax_kernel(const float* __restrict__ temperature) {
    int bh = blockIdx.x, b = bh >> 3, h = bh & 7;
    int d = threadIdx.x;
    __shared__ float rk_s[64];
    rk_s[d] = g_rnorm[b * 1024 + 512 + h * 64 + d];
    __syncthreads();
    float rq = g_rnorm[b * 1024 + h * 64 + d];
    float pref = 8.0f * expf(temperature[h]) * rq;
    float row[64];
    float mx = -1e30f;
#pragma unroll
    for (int e = 0; e < 64; e++) {
        float s = 0.0f;
#pragma unroll
        for (int sp = 0; sp < NSPLIT; sp++)
            s += g_part[(((size_t)sp * 64 + bh) * 64 + d) * 64 + e];
        s *= pref * rk_s[e];
        row[e] = s;
        mx = fmaxf(mx, s);
    }
    float sum = 0.0f;
#pragma unroll
    for (int e = 0; e < 64; e++) {
        float v = expf(row[e] - mx);
        row[e] = v;
        sum += v;
    }
    float inv = 1.0f / sum;
#pragma unroll
    for (int e = 0; e < 64; e++)
        g_attn[((size_t)bh * 64 + d) * 64 + e] = row[e] * inv;
}

// ---------------- K3c: out[d,n] = sum_e attn[d,e] v[e,n] -> y[b,n,h*64+d] ----------------
__global__ __launch_bounds__(256) void av_kernel() {
    int bh = blockIdx.y, b = bh >> 3, h = bh & 7;
    int n0 = blockIdx.x * 64;
    __shared__ float attn_s[64][68];
    __shared__ float vs[64][68];
    int tid = threadIdx.x;
    {
        int d = tid >> 2, e0 = (tid & 3) * 16;
        const float* ap = g_attn + ((size_t)bh * 64 + d) * 64 + e0;
#pragma unroll
        for (int i = 0; i < 16; i++) attn_s[e0 + i][d] = ap[i];
    }
    {
        int e4 = tid & 15, lnl = tid >> 4;
        const float* vbase = g_qkv + (size_t)b * NSEQ * TRIPLE + 1024 + h * 64 + e4 * 4;
#pragma unroll
        for (int p = 0; p < 4; p++) {
            int nl = lnl + p * 16;
            float4 v4 = *reinterpret_cast<const float4*>(vbase + (size_t)(n0 + nl) * TRIPLE);
            vs[e4 * 4 + 0][nl] = v4.x;
            vs[e4 * 4 + 1][nl] = v4.y;
            vs[e4 * 4 + 2][nl] = v4.z;
            vs[e4 * 4 + 3][nl] = v4.w;
        }
    }
    __syncthreads();
    int tx = tid & 15, ty = tid >> 4;
    int d0 = tx * 4, nl0 = ty * 4;
    float c[4][4];
#pragma unroll
    for (int i = 0; i < 4; i++)
#pragma unroll
        for (int j = 0; j < 4; j++) c[i][j] = 0.0f;
#pragma unroll
    for (int e = 0; e < 64; e++) {
        float4 a  = *reinterpret_cast<const float4*>(&attn_s[e][d0]);
        float4 v4 = *reinterpret_cast<const float4*>(&vs[e][nl0]);
        c[0][0] += a.x * v4.x; c[0][1] += a.x * v4.y; c[0][2] += a.x * v4.z; c[0][3] += a.x * v4.w;
        c[1][0] += a.y * v4.x; c[1][1] += a.y * v4.y; c[1][2] += a.y * v4.z; c[1][3] += a.y * v4.w;
        c[2][0] += a.z * v4.x; c[2][1] += a.z * v4.y; c[2][2] += a.z * v4.z; c[2][3] += a.z * v4.w;
        c[3][0] += a.w * v4.x; c[3][1] += a.w * v4.y; c[3][2] += a.w * v4.z; c[3][3] += a.w * v4.w;
    }
#pragma unroll
    for (int j = 0; j < 4; j++) {
        float4 o = make_float4(c[0][j], c[1][j], c[2][j], c[3][j]);
        *reinterpret_cast<float4*>(g_y + (size_t)(b * NSEQ + n0 + nl0 + j) * DIM + h * 64 + d0) = o;
    }
}

// ---------------- launch ----------------
extern "C" void kernel_launch(void* const* d_in, const int* in_sizes, int n_in,
                              void* d_out, int out_size) {
    const float* x           = (const float*)d_in[0];
    const float* gamma       = (const float*)d_in[1];
    const float* w_qkv       = (const float*)d_in[2];
    const float* temperature = (const float*)d_in[3];
    const float* w_out       = (const float*)d_in[4];
    float* out = (float*)d_out;

    float *p_qkv = nullptr, *p_y = nullptr;
    __nv_bfloat16 *p_ahi, *p_alo, *p_yhi, *p_ylo, *p_w1hi, *p_w1lo, *p_w2hi, *p_w2lo;
    cudaGetSymbolAddress((void**)&p_qkv, g_qkv);
    cudaGetSymbolAddress((void**)&p_y, g_y);
    cudaGetSymbolAddress((void**)&p_ahi, g_ahi);
    cudaGetSymbolAddress((void**)&p_alo, g_alo);
    cudaGetSymbolAddress((void**)&p_yhi, g_yhi);
    cudaGetSymbolAddress((void**)&p_ylo, g_ylo);
    cudaGetSymbolAddress((void**)&p_w1hi, g_w1hi);
    cudaGetSymbolAddress((void**)&p_w1lo, g_w1lo);
    cudaGetSymbolAddress((void**)&p_w2hi, g_w2hi);
    cudaGetSymbolAddress((void**)&p_w2lo, g_w2lo);

    // 1) row norms; 2) split A (norm fused) and weights into bf16 hi/lo
    rownorm_kernel<<<MROWS, 128>>>(x);
    convert_a_kernel<<<(MROWS * DIM / 4) / 256, 256>>>(x, gamma);
    split_kernel<<<(DIM * TRIPLE / 4) / 256, 256>>>(w_qkv, p_w1hi, p_w1lo);
    split_kernel<<<(DIM * DIM / 4) / 256, 256>>>(w_out, p_w2hi, p_w2lo);
    // 3) GEMM1 on tensor cores: qkv = A @ w_qkv
    wmma_gemm<<<dim3(TRIPLE / 64, MROWS / 128), 256>>>(
        p_ahi, p_alo, p_w1hi, p_w1lo, p_qkv, TRIPLE, DIM);
    // 4) per-(b,feature) L2 norms of q,k over n
    colnorm_kernel<<<dim3(32, B_), 256>>>();
    // 5) partial Gram matrices
    sim_partial_kernel<<<dim3(64, NSPLIT), 256>>>();
    // 6) reduce + scale + softmax
    softmax_kernel<<<64, 64>>>(temperature);
    // 7) attn @ v
    av_kernel<<<dim3(NSEQ / 64, 64), 256>>>();
    // 8) split y, GEMM2 on tensor cores: out = y @ w_out
    split_kernel<<<(MROWS * DIM / 4) / 256, 256>>>(p_y, p_yhi, p_ylo);
    wmma_gemm<<<dim3(DIM / 64, MROWS / 128), 256>>>(
        p_yhi, p_ylo, p_w2hi, p_w2lo, out, DIM, DIM);
}